// round 14
// baseline (speedup 1.0000x reference)
#include <cuda_runtime.h>
#include <cuda_fp16.h>
#include <math.h>
#include <cstdint>

#define B_   2
#define S_   2048
#define D_   1024
#define H_   16
#define HD_  64
#define M_   (B_ * S_)      // 4096
#define NQKV (3 * D_)       // 3072

// ---------------- scratch (static device globals; no allocation) ----------
__device__ float  g_qkv[(size_t)M_ * NQKV];      // fp32 [B*S, 3D]
__device__ __half g_x16[(size_t)M_ * D_];
__device__ __half g_wq16[(size_t)NQKV * D_];
__device__ __half g_wo16[(size_t)D_ * D_];
__device__ __half g_q16[(size_t)M_ * D_];        // [B,H,S,64]
__device__ __half g_k16[(size_t)M_ * D_];        // [B,H,S,64]
__device__ __half g_v16[(size_t)M_ * D_];        // [B,H,S,64]
__device__ __half g_o16[(size_t)M_ * D_];        // [B*S, D]
__device__ float  g_invfreq[32];

// =====================  helpers  ===========================================
__device__ __forceinline__ uint32_t smem_u32(const void* p) {
    uint32_t a;
    asm("{ .reg .u64 t; cvta.to.shared.u64 t, %1; cvt.u32.u64 %0, t; }"
        : "=r"(a) : "l"(p));
    return a;
}
__device__ __forceinline__ void ldm_x4(uint32_t (&r)[4], uint32_t addr) {
    asm volatile("ldmatrix.sync.aligned.m8n8.x4.shared.b16 {%0,%1,%2,%3}, [%4];"
        : "=r"(r[0]), "=r"(r[1]), "=r"(r[2]), "=r"(r[3]) : "r"(addr));
}
__device__ __forceinline__ void ldm_x4_t(uint32_t (&r)[4], uint32_t addr) {
    asm volatile("ldmatrix.sync.aligned.m8n8.x4.trans.shared.b16 {%0,%1,%2,%3}, [%4];"
        : "=r"(r[0]), "=r"(r[1]), "=r"(r[2]), "=r"(r[3]) : "r"(addr));
}
__device__ __forceinline__ void mma_f16(float (&d)[4], const uint32_t (&a)[4],
                                        uint32_t b0, uint32_t b1) {
    asm volatile(
        "mma.sync.aligned.m16n8k16.row.col.f32.f16.f16.f32 "
        "{%0,%1,%2,%3}, {%4,%5,%6,%7}, {%8,%9}, {%0,%1,%2,%3};"
        : "+f"(d[0]), "+f"(d[1]), "+f"(d[2]), "+f"(d[3])
        : "r"(a[0]), "r"(a[1]), "r"(a[2]), "r"(a[3]), "r"(b0), "r"(b1));
}
__device__ __forceinline__ void cp16(uint32_t saddr, const void* gaddr) {
    asm volatile("cp.async.cg.shared.global [%0], [%1], 16;"
        :: "r"(saddr), "l"(gaddr));
}
#define CP_COMMIT() asm volatile("cp.async.commit_group;" ::: "memory")
#define CP_WAIT(n)  asm volatile("cp.async.wait_group %0;" :: "n"(n) : "memory")

__device__ __forceinline__ uint32_t pack_h2(float x0, float x1) {
    __half2 h = __floats2half2_rn(x0, x1);
    return *(uint32_t*)&h;
}

// ---------------------------------------------------------------------------
__global__ void init_invfreq(float* invf) {
    int j = threadIdx.x;                    // 0..31
    float tt = (float)(2 * j) * (1.0f / (float)HD_);
    invf[j] = powf(10000.0f, -tt);
}

// ---------------------------------------------------------------------------
// cvt fp32 -> fp16 (rn), 8 elems/thread
// ---------------------------------------------------------------------------
__global__ void cvt_f16(const float* __restrict__ src, __half* __restrict__ dst,
                        int n8)
{
    int i = blockIdx.x * blockDim.x + threadIdx.x;
    if (i >= n8) return;
    float4 a = ((const float4*)src)[i * 2];
    float4 b = ((const float4*)src)[i * 2 + 1];
    uint4 o;
    o.x = pack_h2(a.x, a.y);
    o.y = pack_h2(a.z, a.w);
    o.z = pack_h2(b.x, b.y);
    o.w = pack_h2(b.z, b.w);
    ((uint4*)dst)[i] = o;
}

// ---------------------------------------------------------------------------
// GEMM (NT) fp16: CTA 128x128, 8 warps, warp tile 64x32. K-chunk 64,
// 3-stage cp.async (32KB/stage), 2 CTAs/SM. (unchanged from round 12)
// ---------------------------------------------------------------------------
#define G_BOFF 16384
#define G_STG  32768
#define GEMM_SMEM (3 * G_STG)      // 98304

__global__ void __launch_bounds__(256, 2) gemm_f16(
    const __half* __restrict__ A, const __half* __restrict__ Bw,
    const float* __restrict__ bias, float* __restrict__ C,
    int M, int N, int K)
{
    extern __shared__ char sm[];
    const uint32_t sb = smem_u32(sm);
    const int tid  = threadIdx.x;
    const int lane = tid & 31;
    const int w    = tid >> 5;
    const int m0 = blockIdx.y * 128;
    const int n0 = blockIdx.x * 128;
    const int wm = (w & 1) * 64;
    const int wn = (w >> 1) * 32;

    float acc[4][4][4];
#pragma unroll
    for (int mi = 0; mi < 4; ++mi)
#pragma unroll
        for (int nj = 0; nj < 4; ++nj)
#pragma unroll
            for (int q = 0; q < 4; ++q) acc[mi][nj][q] = 0.f;

    const int nch = K >> 6;

    auto issue = [&](int kc, int stg) {
        uint32_t st = sb + stg * G_STG;
#pragma unroll
        for (int it = 0; it < 4; ++it) {
            int idx = tid + it * 256;
            int r = idx >> 3, c = idx & 7;
            uint32_t so = r * 128 + (((uint32_t)(c ^ (r & 7))) << 4);
            cp16(st + so, A + (size_t)(m0 + r) * K + kc * 64 + c * 8);
        }
#pragma unroll
        for (int it = 0; it < 4; ++it) {
            int idx = tid + it * 256;
            int r = idx >> 3, c = idx & 7;
            uint32_t so = r * 128 + (((uint32_t)(c ^ (r & 7))) << 4);
            cp16(st + G_BOFF + so, Bw + (size_t)(n0 + r) * K + kc * 64 + c * 8);
        }
        CP_COMMIT();
    };

    issue(0, 0);
    if (nch > 1) issue(1, 1);

    const int arow = (lane & 7) + ((lane >> 3) & 1) * 8;
    const int asel = lane >> 4;
    const int brow = (lane & 7) + ((lane >> 4) & 1) * 8;
    const int bsel = (lane >> 3) & 1;

    for (int kc = 0; kc < nch; ++kc) {
        if (kc + 1 < nch) { CP_WAIT(1); }
        else              { CP_WAIT(0); }
        __syncthreads();
        if (kc + 2 < nch) issue(kc + 2, (kc + 2) % 3);
        const uint32_t st = sb + (kc % 3) * G_STG;

#pragma unroll
        for (int ks = 0; ks < 4; ++ks) {
            uint32_t bf[4][2];
#pragma unroll
            for (int pi = 0; pi < 2; ++pi) {
                int r = wn + pi * 16 + brow;
                int gc = ks * 2 + bsel;
                uint32_t ad = st + G_BOFF + r * 128 +
                              (((uint32_t)(gc ^ (r & 7))) << 4);
                uint32_t tr[4];
                ldm_x4(tr, ad);
                bf[pi*2][0] = tr[0]; bf[pi*2][1] = tr[1];
                bf[pi*2+1][0] = tr[2]; bf[pi*2+1][1] = tr[3];
            }
#pragma unroll
            for (int mi = 0; mi < 4; ++mi) {
                int r = wm + mi * 16 + arow;
                int gc = ks * 2 + asel;
                uint32_t ad = st + r * 128 + (((uint32_t)(gc ^ (r & 7))) << 4);
                uint32_t af[4];
                ldm_x4(af, ad);
#pragma unroll
                for (int nj = 0; nj < 4; ++nj)
                    mma_f16(acc[mi][nj], af, bf[nj][0], bf[nj][1]);
            }
        }
    }

    const int g = lane >> 2;
    const int c0 = (lane & 3) * 2;
#pragma unroll
    for (int mi = 0; mi < 4; ++mi) {
#pragma unroll
        for (int nj = 0; nj < 4; ++nj) {
            int m = m0 + wm + mi * 16 + g;
            int n = n0 + wn + nj * 8 + c0;
            float b0 = bias ? bias[n] : 0.f;
            float b1 = bias ? bias[n + 1] : 0.f;
            float2 v0 = {acc[mi][nj][0] + b0, acc[mi][nj][1] + b1};
            float2 v1 = {acc[mi][nj][2] + b0, acc[mi][nj][3] + b1};
            *(float2*)(C + (size_t)m * N + n)       = v0;
            *(float2*)(C + (size_t)(m + 8) * N + n) = v1;
        }
    }
}

// ---------------------------------------------------------------------------
// RoPE: fp32 qkv -> fp16 q/k/v in [B,H,S,64]. (unchanged)
// ---------------------------------------------------------------------------
__global__ void rope_f16(const float* __restrict__ qkv,
                         const float* __restrict__ invfreq,
                         __half* __restrict__ q16, __half* __restrict__ k16,
                         __half* __restrict__ v16)
{
    int idx = blockIdx.x * blockDim.x + threadIdx.x;
    if (idx >= B_ * S_ * H_ * 32) return;
    int j = idx & 31;
    int h = (idx >> 5) & (H_ - 1);
    int s = (idx >> 9) & (S_ - 1);
    int b = idx >> 20;

    float ang = (float)s * invfreq[j];
    float cs, sn;
    sincosf(ang, &sn, &cs);

    const float* row = qkv + ((size_t)(b * S_ + s)) * NQKV + h * HD_;
    float q1 = row[2 * j],          q2 = row[2 * j + 1];
    float k1 = row[D_ + 2 * j],     k2 = row[D_ + 2 * j + 1];
    float v1 = row[2 * D_ + 2 * j], v2 = row[2 * D_ + 2 * j + 1];

    size_t o = (((size_t)(b * H_ + h)) * S_ + s) * HD_;
    const float qs = 0.125f;
    q16[o + j]      = __float2half_rn((q1 * cs - q2 * sn) * qs);
    q16[o + 32 + j] = __float2half_rn((q1 * sn + q2 * cs) * qs);
    k16[o + j]      = __float2half_rn(k1 * cs - k2 * sn);
    k16[o + 32 + j] = __float2half_rn(k1 * sn + k2 * cs);
    __half2 vv = __floats2half2_rn(v1, v2);
    *(__half2*)(v16 + o + 2 * j) = vv;
}

// ---------------------------------------------------------------------------
// Flash attention fp16. 128 threads (4 warps), 32 q-rows/warp (q-tile 128),
// kv-tile 32, 4-stage cp.async (8KB/stage), 3 CTAs/SM.
// ---------------------------------------------------------------------------
#define A_VOFF 4096
#define A_STG  8192
#define ATT_SMEM (4 * A_STG)       // 32768

__global__ void __launch_bounds__(128, 3) attn_f16(
    const __half* __restrict__ q_, const __half* __restrict__ k_,
    const __half* __restrict__ v_, __half* __restrict__ o_)
{
    extern __shared__ char sm[];
    const uint32_t sb = smem_u32(sm);
    const int tid  = threadIdx.x;
    const int lane = tid & 31;
    const int w    = tid >> 5;
    const int g    = lane >> 2;
    const int t    = lane & 3;
    const int q0 = blockIdx.x * 128;
    const int h  = blockIdx.y;
    const int b  = blockIdx.z;
    const size_t bh = ((size_t)(b * H_ + h)) * S_;

    const int frow = (lane & 7) + ((lane >> 3) & 1) * 8;
    const int fsel = lane >> 4;
    const int brow = (lane & 7) + ((lane >> 4) & 1) * 8;
    const int bsel = (lane >> 3) & 1;
    const int vrow = (lane & 7) + ((lane >> 3) & 1) * 8;
    const int vsel = lane >> 4;

    // --- stage Q (128 rows x 128B = 16KB) into stages 0-1, extract frags ---
#pragma unroll
    for (int it = 0; it < 8; ++it) {
        int idx = tid + it * 128;          // 1024: 128 rows x 8 chunks
        int r = idx >> 3, c = idx & 7;
        uint32_t so = r * 128 + (((uint32_t)(c ^ (r & 7))) << 4);
        cp16(sb + so, q_ + (bh + q0 + r) * HD_ + c * 8);
    }
    CP_COMMIT();
    CP_WAIT(0);
    __syncthreads();

    uint32_t qf[2][4][4];                  // [16-row half][k16][regs]
#pragma unroll
    for (int rs = 0; rs < 2; ++rs) {
        int r = w * 32 + rs * 16 + frow;
#pragma unroll
        for (int ks = 0; ks < 4; ++ks) {
            int gc = ks * 2 + fsel;
            uint32_t ad = sb + r * 128 + (((uint32_t)(gc ^ (r & 7))) << 4);
            ldm_x4(qf[rs][ks], ad);
        }
    }
    __syncthreads();   // everyone done reading Q region

    auto issue_kv = [&](int n0k, int stg) {
        uint32_t st = sb + stg * A_STG;
#pragma unroll
        for (int it = 0; it < 2; ++it) {   // K: 32 rows x 8 chunks = 256
            int idx = tid + it * 128;
            int r = idx >> 3, c = idx & 7;
            uint32_t so = r * 128 + (((uint32_t)(c ^ (r & 7))) << 4);
            cp16(st + so, k_ + (bh + n0k + r) * HD_ + c * 8);
        }
#pragma unroll
        for (int it = 0; it < 2; ++it) {   // V: 32 rows x 8 chunks = 256
            int idx = tid + it * 128;
            int r = idx >> 3, c = idx & 7;
            uint32_t so = r * 128 + (((uint32_t)(c ^ (r & 7))) << 4);
            cp16(st + A_VOFF + so, v_ + (bh + n0k + r) * HD_ + c * 8);
        }
        CP_COMMIT();
    };

    issue_kv(0, 0);
    issue_kv(32, 1);
    issue_kv(64, 2);

    float oacc[2][8][4];
    float mx[2][2] = {{-1e30f, -1e30f}, {-1e30f, -1e30f}};
    float li[2][2] = {{0.f, 0.f}, {0.f, 0.f}};
#pragma unroll
    for (int rs = 0; rs < 2; ++rs)
#pragma unroll
        for (int dj = 0; dj < 8; ++dj)
#pragma unroll
            for (int q = 0; q < 4; ++q) oacc[rs][dj][q] = 0.f;

    const int nkv = S_ / 32;
    for (int kc = 0; kc < nkv; ++kc) {
        if (kc + 2 < nkv) { CP_WAIT(2); }
        else if (kc + 1 < nkv) { CP_WAIT(1); }
        else { CP_WAIT(0); }
        __syncthreads();
        if (kc + 3 < nkv) issue_kv((kc + 3) * 32, (kc + 3) & 3);
        const uint32_t st = sb + (kc & 3) * A_STG;

        // ---- S = Q K^T : per warp 32q x 32kv ----
        float s[2][4][4];
#pragma unroll
        for (int rs = 0; rs < 2; ++rs)
#pragma unroll
            for (int nj = 0; nj < 4; ++nj)
#pragma unroll
                for (int q = 0; q < 4; ++q) s[rs][nj][q] = 0.f;

#pragma unroll
        for (int ks = 0; ks < 4; ++ks) {
            uint32_t kf[4][2];
#pragma unroll
            for (int pi = 0; pi < 2; ++pi) {
                int r = pi * 16 + brow;
                int gc = ks * 2 + bsel;
                uint32_t ad = st + r * 128 + (((uint32_t)(gc ^ (r & 7))) << 4);
                uint32_t tr[4];
                ldm_x4(tr, ad);
                kf[pi*2][0] = tr[0]; kf[pi*2][1] = tr[1];
                kf[pi*2+1][0] = tr[2]; kf[pi*2+1][1] = tr[3];
            }
#pragma unroll
            for (int rs = 0; rs < 2; ++rs)
#pragma unroll
                for (int nj = 0; nj < 4; ++nj)
                    mma_f16(s[rs][nj], qf[rs][ks], kf[nj][0], kf[nj][1]);
        }

        // ---- online softmax ----
#pragma unroll
        for (int rs = 0; rs < 2; ++rs) {
#pragma unroll
            for (int ri = 0; ri < 2; ++ri) {
                float rm = -1e30f;
#pragma unroll
                for (int nj = 0; nj < 4; ++nj)
                    rm = fmaxf(rm, fmaxf(s[rs][nj][ri*2], s[rs][nj][ri*2+1]));
                rm = fmaxf(rm, __shfl_xor_sync(0xffffffffu, rm, 1));
                rm = fmaxf(rm, __shfl_xor_sync(0xffffffffu, rm, 2));
                float mn   = fmaxf(mx[rs][ri], rm);
                float corr = __expf(mx[rs][ri] - mn);
                mx[rs][ri] = mn;
                float rsum = 0.f;
#pragma unroll
                for (int nj = 0; nj < 4; ++nj) {
                    float p0 = __expf(s[rs][nj][ri*2]   - mn);
                    float p1 = __expf(s[rs][nj][ri*2+1] - mn);
                    s[rs][nj][ri*2] = p0; s[rs][nj][ri*2+1] = p1;
                    rsum += p0 + p1;
                }
                rsum += __shfl_xor_sync(0xffffffffu, rsum, 1);
                rsum += __shfl_xor_sync(0xffffffffu, rsum, 2);
                li[rs][ri] = li[rs][ri] * corr + rsum;
#pragma unroll
                for (int dj = 0; dj < 8; ++dj) {
                    oacc[rs][dj][ri*2]   *= corr;
                    oacc[rs][dj][ri*2+1] *= corr;
                }
            }
        }

        // ---- O += P V ----
#pragma unroll
        for (int kk = 0; kk < 2; ++kk) {   // k16 tiles over kv 32
            uint32_t pa[2][4];
#pragma unroll
            for (int rs = 0; rs < 2; ++rs) {
                pa[rs][0] = pack_h2(s[rs][kk*2][0],   s[rs][kk*2][1]);
                pa[rs][1] = pack_h2(s[rs][kk*2][2],   s[rs][kk*2][3]);
                pa[rs][2] = pack_h2(s[rs][kk*2+1][0], s[rs][kk*2+1][1]);
                pa[rs][3] = pack_h2(s[rs][kk*2+1][2], s[rs][kk*2+1][3]);
            }
#pragma unroll
            for (int pj = 0; pj < 4; ++pj) {   // d-chunks: 2 dj per ldm
                int r = kk * 16 + vrow;
                int gc = pj * 2 + vsel;
                uint32_t ad = st + A_VOFF + r * 128 +
                              (((uint32_t)(gc ^ (r & 7))) << 4);
                uint32_t tv[4];
                ldm_x4_t(tv, ad);
#pragma unroll
                for (int rs = 0; rs < 2; ++rs) {
                    mma_f16(oacc[rs][pj*2],   pa[rs], tv[0], tv[1]);
                    mma_f16(oacc[rs][pj*2+1], pa[rs], tv[2], tv[3]);
                }
            }
        }
    }

    // ---- epilogue: normalize, fp16 store [B*S, D] ----
#pragma unroll
    for (int rs = 0; rs < 2; ++rs) {
#pragma unroll
        for (int ri = 0; ri < 2; ++ri) {
            float inv = 1.0f / li[rs][ri];
            int srow = q0 + w * 32 + rs * 16 + g + ri * 8;
            size_t rowo = ((size_t)(b * S_) + srow) * D_ + h * HD_;
#pragma unroll
            for (int dj = 0; dj < 8; ++dj) {
                int c = dj * 8 + 2 * t;
                uint32_t hp = pack_h2(oacc[rs][dj][ri*2] * inv,
                                      oacc[rs][dj][ri*2+1] * inv);
                *(uint32_t*)(o_ + rowo + c) = hp;
            }
        }
    }
}

// ---------------------------------------------------------------------------
extern "C" void kernel_launch(void* const* d_in, const int* in_sizes, int n_in,
                              void* d_out, int out_size)
{
    (void)in_sizes; (void)n_in; (void)out_size;
    const float* x     = (const float*)d_in[0];
    const float* w_qkv = (const float*)d_in[1];
    const float* w_out = (const float*)d_in[2];
    const float* b_out = (const float*)d_in[3];
    float* out = (float*)d_out;

    float *p_qkv, *p_if;
    __half *p_x, *p_wq, *p_wo, *p_q, *p_k, *p_v, *p_o;
    cudaGetSymbolAddress((void**)&p_qkv, g_qkv);
    cudaGetSymbolAddress((void**)&p_if,  g_invfreq);
    cudaGetSymbolAddress((void**)&p_x,   g_x16);
    cudaGetSymbolAddress((void**)&p_wq,  g_wq16);
    cudaGetSymbolAddress((void**)&p_wo,  g_wo16);
    cudaGetSymbolAddress((void**)&p_q,   g_q16);
    cudaGetSymbolAddress((void**)&p_k,   g_k16);
    cudaGetSymbolAddress((void**)&p_v,   g_v16);
    cudaGetSymbolAddress((void**)&p_o,   g_o16);

    cudaFuncSetAttribute(gemm_f16,
        cudaFuncAttributeMaxDynamicSharedMemorySize, GEMM_SMEM);
    cudaFuncSetAttribute(attn_f16,
        cudaFuncAttributeMaxDynamicSharedMemorySize, ATT_SMEM);

    // 0) rope table + convert inputs / weights to fp16
    init_invfreq<<<1, 32>>>(p_if);
    {
        int n8;
        n8 = (M_ * D_) / 8;
        cvt_f16<<<(n8 + 255) / 256, 256>>>(x, p_x, n8);
        n8 = (NQKV * D_) / 8;
        cvt_f16<<<(n8 + 255) / 256, 256>>>(w_qkv, p_wq, n8);
        n8 = (D_ * D_) / 8;
        cvt_f16<<<(n8 + 255) / 256, 256>>>(w_out, p_wo, n8);
    }
    // 1) QKV projection (fp16 in, fp32 out)
    {
        dim3 grid(NQKV / 128, M_ / 128);
        gemm_f16<<<grid, 256, GEMM_SMEM>>>(p_x, p_wq, nullptr, p_qkv,
                                           M_, NQKV, D_);
    }
    // 2) RoPE -> fp16 q/k/v [B,H,S,64]
    {
        int total = B_ * S_ * H_ * 32;
        rope_f16<<<(total + 255) / 256, 256>>>(p_qkv, p_if, p_q, p_k, p_v);
    }
    // 3) flash attention (fp16 tensor cores)
    {
        dim3 grid(S_ / 128, H_, B_);
        attn_f16<<<grid, 128, ATT_SMEM>>>(p_q, p_k, p_v, p_o);
    }
    // 4) output projection + bias
    {
        dim3 grid(D_ / 128, M_ / 128);
        gemm_f16<<<grid, 256, GEMM_SMEM>>>(p_o, p_wo, b_out, out,
                                           M_, D_, D_);
    }
}

// round 15
// speedup vs baseline: 1.1022x; 1.1022x over previous
#include <cuda_runtime.h>
#include <cuda_fp16.h>
#include <math.h>
#include <cstdint>

#define B_   2
#define S_   2048
#define D_   1024
#define H_   16
#define HD_  64
#define M_   (B_ * S_)      // 4096
#define NQKV (3 * D_)       // 3072

// ---------------- scratch (static device globals; no allocation) ----------
__device__ float  g_qkv[(size_t)M_ * NQKV];      // fp32 [B*S, 3D]
__device__ __half g_x16[(size_t)M_ * D_];
__device__ __half g_wq16[(size_t)NQKV * D_];
__device__ __half g_wo16[(size_t)D_ * D_];
__device__ __half g_q16[(size_t)M_ * D_];        // [B,H,S,64]
__device__ __half g_k16[(size_t)M_ * D_];        // [B,H,S,64]
__device__ __half g_v16[(size_t)M_ * D_];        // [B,H,S,64]
__device__ __half g_o16[(size_t)M_ * D_];        // [B*S, D]
__device__ float  g_invfreq[32];

// =====================  helpers  ===========================================
__device__ __forceinline__ uint32_t smem_u32(const void* p) {
    uint32_t a;
    asm("{ .reg .u64 t; cvta.to.shared.u64 t, %1; cvt.u32.u64 %0, t; }"
        : "=r"(a) : "l"(p));
    return a;
}
__device__ __forceinline__ void ldm_x4(uint32_t (&r)[4], uint32_t addr) {
    asm volatile("ldmatrix.sync.aligned.m8n8.x4.shared.b16 {%0,%1,%2,%3}, [%4];"
        : "=r"(r[0]), "=r"(r[1]), "=r"(r[2]), "=r"(r[3]) : "r"(addr));
}
__device__ __forceinline__ void ldm_x4_t(uint32_t (&r)[4], uint32_t addr) {
    asm volatile("ldmatrix.sync.aligned.m8n8.x4.trans.shared.b16 {%0,%1,%2,%3}, [%4];"
        : "=r"(r[0]), "=r"(r[1]), "=r"(r[2]), "=r"(r[3]) : "r"(addr));
}
__device__ __forceinline__ void mma_f16(float (&d)[4], const uint32_t (&a)[4],
                                        uint32_t b0, uint32_t b1) {
    asm volatile(
        "mma.sync.aligned.m16n8k16.row.col.f32.f16.f16.f32 "
        "{%0,%1,%2,%3}, {%4,%5,%6,%7}, {%8,%9}, {%0,%1,%2,%3};"
        : "+f"(d[0]), "+f"(d[1]), "+f"(d[2]), "+f"(d[3])
        : "r"(a[0]), "r"(a[1]), "r"(a[2]), "r"(a[3]), "r"(b0), "r"(b1));
}
__device__ __forceinline__ void cp16(uint32_t saddr, const void* gaddr) {
    asm volatile("cp.async.cg.shared.global [%0], [%1], 16;"
        :: "r"(saddr), "l"(gaddr));
}
#define CP_COMMIT() asm volatile("cp.async.commit_group;" ::: "memory")
#define CP_WAIT(n)  asm volatile("cp.async.wait_group %0;" :: "n"(n) : "memory")

__device__ __forceinline__ uint32_t pack_h2(float x0, float x1) {
    __half2 h = __floats2half2_rn(x0, x1);
    return *(uint32_t*)&h;
}

// ---------------------------------------------------------------------------
__global__ void init_invfreq(float* invf) {
    int j = threadIdx.x;                    // 0..31
    float tt = (float)(2 * j) * (1.0f / (float)HD_);
    invf[j] = powf(10000.0f, -tt);
}

// ---------------------------------------------------------------------------
// segmented cvt fp32 -> fp16 (rn), 8 elems/thread, one launch for 3 arrays.
// segments (in units of 8 elements): x = [0, S0), wqkv = [S0, S1), wout = [S1, S2)
// ---------------------------------------------------------------------------
#define CVT_S0 ((M_ * D_) / 8)
#define CVT_S1 (CVT_S0 + (NQKV * D_) / 8)
#define CVT_S2 (CVT_S1 + (D_ * D_) / 8)

__global__ void cvt_f16_all(const float* __restrict__ x,
                            const float* __restrict__ wq,
                            const float* __restrict__ wo,
                            __half* __restrict__ x16,
                            __half* __restrict__ wq16,
                            __half* __restrict__ wo16)
{
    int i = blockIdx.x * blockDim.x + threadIdx.x;
    if (i >= CVT_S2) return;
    const float* src;
    __half* dst;
    int off;
    if (i < CVT_S0)       { src = x;  dst = x16;  off = i; }
    else if (i < CVT_S1)  { src = wq; dst = wq16; off = i - CVT_S0; }
    else                  { src = wo; dst = wo16; off = i - CVT_S1; }
    float4 a = ((const float4*)src)[off * 2];
    float4 b = ((const float4*)src)[off * 2 + 1];
    uint4 o;
    o.x = pack_h2(a.x, a.y);
    o.y = pack_h2(a.z, a.w);
    o.z = pack_h2(b.x, b.y);
    o.w = pack_h2(b.z, b.w);
    ((uint4*)dst)[off] = o;
}

// ---------------------------------------------------------------------------
// GEMM (NT) fp16: CTA 128x128, 8 warps, warp tile 64x32. K-chunk 64,
// 3-stage cp.async (32KB/stage), 2 CTAs/SM. (round 12, proven)
// ---------------------------------------------------------------------------
#define G_BOFF 16384
#define G_STG  32768
#define GEMM_SMEM (3 * G_STG)      // 98304

__global__ void __launch_bounds__(256, 2) gemm_f16(
    const __half* __restrict__ A, const __half* __restrict__ Bw,
    const float* __restrict__ bias, float* __restrict__ C,
    int M, int N, int K)
{
    extern __shared__ char sm[];
    const uint32_t sb = smem_u32(sm);
    const int tid  = threadIdx.x;
    const int lane = tid & 31;
    const int w    = tid >> 5;
    const int m0 = blockIdx.y * 128;
    const int n0 = blockIdx.x * 128;
    const int wm = (w & 1) * 64;
    const int wn = (w >> 1) * 32;

    float acc[4][4][4];
#pragma unroll
    for (int mi = 0; mi < 4; ++mi)
#pragma unroll
        for (int nj = 0; nj < 4; ++nj)
#pragma unroll
            for (int q = 0; q < 4; ++q) acc[mi][nj][q] = 0.f;

    const int nch = K >> 6;

    auto issue = [&](int kc, int stg) {
        uint32_t st = sb + stg * G_STG;
#pragma unroll
        for (int it = 0; it < 4; ++it) {
            int idx = tid + it * 256;
            int r = idx >> 3, c = idx & 7;
            uint32_t so = r * 128 + (((uint32_t)(c ^ (r & 7))) << 4);
            cp16(st + so, A + (size_t)(m0 + r) * K + kc * 64 + c * 8);
        }
#pragma unroll
        for (int it = 0; it < 4; ++it) {
            int idx = tid + it * 256;
            int r = idx >> 3, c = idx & 7;
            uint32_t so = r * 128 + (((uint32_t)(c ^ (r & 7))) << 4);
            cp16(st + G_BOFF + so, Bw + (size_t)(n0 + r) * K + kc * 64 + c * 8);
        }
        CP_COMMIT();
    };

    issue(0, 0);
    if (nch > 1) issue(1, 1);

    const int arow = (lane & 7) + ((lane >> 3) & 1) * 8;
    const int asel = lane >> 4;
    const int brow = (lane & 7) + ((lane >> 4) & 1) * 8;
    const int bsel = (lane >> 3) & 1;

    for (int kc = 0; kc < nch; ++kc) {
        if (kc + 1 < nch) { CP_WAIT(1); }
        else              { CP_WAIT(0); }
        __syncthreads();
        if (kc + 2 < nch) issue(kc + 2, (kc + 2) % 3);
        const uint32_t st = sb + (kc % 3) * G_STG;

#pragma unroll
        for (int ks = 0; ks < 4; ++ks) {
            uint32_t bf[4][2];
#pragma unroll
            for (int pi = 0; pi < 2; ++pi) {
                int r = wn + pi * 16 + brow;
                int gc = ks * 2 + bsel;
                uint32_t ad = st + G_BOFF + r * 128 +
                              (((uint32_t)(gc ^ (r & 7))) << 4);
                uint32_t tr[4];
                ldm_x4(tr, ad);
                bf[pi*2][0] = tr[0]; bf[pi*2][1] = tr[1];
                bf[pi*2+1][0] = tr[2]; bf[pi*2+1][1] = tr[3];
            }
#pragma unroll
            for (int mi = 0; mi < 4; ++mi) {
                int r = wm + mi * 16 + arow;
                int gc = ks * 2 + asel;
                uint32_t ad = st + r * 128 + (((uint32_t)(gc ^ (r & 7))) << 4);
                uint32_t af[4];
                ldm_x4(af, ad);
#pragma unroll
                for (int nj = 0; nj < 4; ++nj)
                    mma_f16(acc[mi][nj], af, bf[nj][0], bf[nj][1]);
            }
        }
    }

    const int g = lane >> 2;
    const int c0 = (lane & 3) * 2;
#pragma unroll
    for (int mi = 0; mi < 4; ++mi) {
#pragma unroll
        for (int nj = 0; nj < 4; ++nj) {
            int m = m0 + wm + mi * 16 + g;
            int n = n0 + wn + nj * 8 + c0;
            float b0 = bias ? bias[n] : 0.f;
            float b1 = bias ? bias[n + 1] : 0.f;
            float2 v0 = {acc[mi][nj][0] + b0, acc[mi][nj][1] + b1};
            float2 v1 = {acc[mi][nj][2] + b0, acc[mi][nj][3] + b1};
            *(float2*)(C + (size_t)m * N + n)       = v0;
            *(float2*)(C + (size_t)(m + 8) * N + n) = v1;
        }
    }
}

// ---------------------------------------------------------------------------
// RoPE: fp32 qkv -> fp16 q/k/v in [B,H,S,64]. float2-vectorized loads,
// arithmetic identical to round 12.
// ---------------------------------------------------------------------------
__global__ void rope_f16(const float* __restrict__ qkv,
                         const float* __restrict__ invfreq,
                         __half* __restrict__ q16, __half* __restrict__ k16,
                         __half* __restrict__ v16)
{
    int idx = blockIdx.x * blockDim.x + threadIdx.x;
    if (idx >= B_ * S_ * H_ * 32) return;
    int j = idx & 31;
    int h = (idx >> 5) & (H_ - 1);
    int s = (idx >> 9) & (S_ - 1);
    int b = idx >> 20;

    float ang = (float)s * invfreq[j];
    float cs, sn;
    sincosf(ang, &sn, &cs);

    const float* row = qkv + ((size_t)(b * S_ + s)) * NQKV + h * HD_;
    float2 qv = *(const float2*)(row + 2 * j);
    float2 kv = *(const float2*)(row + D_ + 2 * j);
    float2 vv = *(const float2*)(row + 2 * D_ + 2 * j);

    size_t o = (((size_t)(b * H_ + h)) * S_ + s) * HD_;
    const float qs = 0.125f;
    q16[o + j]      = __float2half_rn((qv.x * cs - qv.y * sn) * qs);
    q16[o + 32 + j] = __float2half_rn((qv.x * sn + qv.y * cs) * qs);
    k16[o + j]      = __float2half_rn(kv.x * cs - kv.y * sn);
    k16[o + 32 + j] = __float2half_rn(kv.x * sn + kv.y * cs);
    __half2 vh = __floats2half2_rn(vv.x, vv.y);
    *(__half2*)(v16 + o + 2 * j) = vh;
}

// ---------------------------------------------------------------------------
// Flash attention fp16. 128 threads (4 warps), 32 q-rows/warp (q-tile 128),
// kv-tile 64, 3-stage cp.async, 2 CTAs/SM. (round 12, proven 244.8us)
// ---------------------------------------------------------------------------
#define A_VOFF 8192
#define A_STG  16384
#define ATT_SMEM (3 * A_STG)       // 49152

__global__ void __launch_bounds__(128, 2) attn_f16(
    const __half* __restrict__ q_, const __half* __restrict__ k_,
    const __half* __restrict__ v_, __half* __restrict__ o_)
{
    extern __shared__ char sm[];
    const uint32_t sb = smem_u32(sm);
    const int tid  = threadIdx.x;
    const int lane = tid & 31;
    const int w    = tid >> 5;
    const int g    = lane >> 2;
    const int t    = lane & 3;
    const int q0 = blockIdx.x * 128;
    const int h  = blockIdx.y;
    const int b  = blockIdx.z;
    const size_t bh = ((size_t)(b * H_ + h)) * S_;

    const int frow = (lane & 7) + ((lane >> 3) & 1) * 8;
    const int fsel = lane >> 4;
    const int brow = (lane & 7) + ((lane >> 4) & 1) * 8;
    const int bsel = (lane >> 3) & 1;
    const int vrow = (lane & 7) + ((lane >> 3) & 1) * 8;
    const int vsel = lane >> 4;

#pragma unroll
    for (int it = 0; it < 8; ++it) {
        int idx = tid + it * 128;
        int r = idx >> 3, c = idx & 7;
        uint32_t so = r * 128 + (((uint32_t)(c ^ (r & 7))) << 4);
        cp16(sb + so, q_ + (bh + q0 + r) * HD_ + c * 8);
    }
    CP_COMMIT();
    CP_WAIT(0);
    __syncthreads();

    uint32_t qf[2][4][4];
#pragma unroll
    for (int rs = 0; rs < 2; ++rs) {
        int r = w * 32 + rs * 16 + frow;
#pragma unroll
        for (int ks = 0; ks < 4; ++ks) {
            int gc = ks * 2 + fsel;
            uint32_t ad = sb + r * 128 + (((uint32_t)(gc ^ (r & 7))) << 4);
            ldm_x4(qf[rs][ks], ad);
        }
    }
    __syncthreads();

    auto issue_kv = [&](int n0k, int stg) {
        uint32_t st = sb + stg * A_STG;
#pragma unroll
        for (int it = 0; it < 4; ++it) {
            int idx = tid + it * 128;
            int r = idx >> 3, c = idx & 7;
            uint32_t so = r * 128 + (((uint32_t)(c ^ (r & 7))) << 4);
            cp16(st + so, k_ + (bh + n0k + r) * HD_ + c * 8);
        }
#pragma unroll
        for (int it = 0; it < 4; ++it) {
            int idx = tid + it * 128;
            int r = idx >> 3, c = idx & 7;
            uint32_t so = r * 128 + (((uint32_t)(c ^ (r & 7))) << 4);
            cp16(st + A_VOFF + so, v_ + (bh + n0k + r) * HD_ + c * 8);
        }
        CP_COMMIT();
    };

    issue_kv(0, 0);
    issue_kv(64, 1);

    float oacc[2][8][4];
    float mx[2][2] = {{-1e30f, -1e30f}, {-1e30f, -1e30f}};
    float li[2][2] = {{0.f, 0.f}, {0.f, 0.f}};
#pragma unroll
    for (int rs = 0; rs < 2; ++rs)
#pragma unroll
        for (int dj = 0; dj < 8; ++dj)
#pragma unroll
            for (int q = 0; q < 4; ++q) oacc[rs][dj][q] = 0.f;

    const int nkv = S_ / 64;
    for (int kc = 0; kc < nkv; ++kc) {
        if (kc + 1 < nkv) { CP_WAIT(1); }
        else              { CP_WAIT(0); }
        __syncthreads();
        if (kc + 2 < nkv) issue_kv((kc + 2) * 64, (kc + 2) % 3);
        const uint32_t st = sb + (kc % 3) * A_STG;

        float s[2][8][4];
#pragma unroll
        for (int rs = 0; rs < 2; ++rs)
#pragma unroll
            for (int nj = 0; nj < 8; ++nj)
#pragma unroll
                for (int q = 0; q < 4; ++q) s[rs][nj][q] = 0.f;

#pragma unroll
        for (int ks = 0; ks < 4; ++ks) {
            uint32_t kf[8][2];
#pragma unroll
            for (int pi = 0; pi < 4; ++pi) {
                int r = pi * 16 + brow;
                int gc = ks * 2 + bsel;
                uint32_t ad = st + r * 128 + (((uint32_t)(gc ^ (r & 7))) << 4);
                uint32_t tr[4];
                ldm_x4(tr, ad);
                kf[pi*2][0] = tr[0]; kf[pi*2][1] = tr[1];
                kf[pi*2+1][0] = tr[2]; kf[pi*2+1][1] = tr[3];
            }
#pragma unroll
            for (int rs = 0; rs < 2; ++rs)
#pragma unroll
                for (int nj = 0; nj < 8; ++nj)
                    mma_f16(s[rs][nj], qf[rs][ks], kf[nj][0], kf[nj][1]);
        }

#pragma unroll
        for (int rs = 0; rs < 2; ++rs) {
#pragma unroll
            for (int ri = 0; ri < 2; ++ri) {
                float rm = -1e30f;
#pragma unroll
                for (int nj = 0; nj < 8; ++nj)
                    rm = fmaxf(rm, fmaxf(s[rs][nj][ri*2], s[rs][nj][ri*2+1]));
                rm = fmaxf(rm, __shfl_xor_sync(0xffffffffu, rm, 1));
                rm = fmaxf(rm, __shfl_xor_sync(0xffffffffu, rm, 2));
                float mn   = fmaxf(mx[rs][ri], rm);
                float corr = __expf(mx[rs][ri] - mn);
                mx[rs][ri] = mn;
                float rsum = 0.f;
#pragma unroll
                for (int nj = 0; nj < 8; ++nj) {
                    float p0 = __expf(s[rs][nj][ri*2]   - mn);
                    float p1 = __expf(s[rs][nj][ri*2+1] - mn);
                    s[rs][nj][ri*2] = p0; s[rs][nj][ri*2+1] = p1;
                    rsum += p0 + p1;
                }
                rsum += __shfl_xor_sync(0xffffffffu, rsum, 1);
                rsum += __shfl_xor_sync(0xffffffffu, rsum, 2);
                li[rs][ri] = li[rs][ri] * corr + rsum;
#pragma unroll
                for (int dj = 0; dj < 8; ++dj) {
                    oacc[rs][dj][ri*2]   *= corr;
                    oacc[rs][dj][ri*2+1] *= corr;
                }
            }
        }

#pragma unroll
        for (int kk = 0; kk < 4; ++kk) {
            uint32_t pa[2][4];
#pragma unroll
            for (int rs = 0; rs < 2; ++rs) {
                pa[rs][0] = pack_h2(s[rs][kk*2][0],   s[rs][kk*2][1]);
                pa[rs][1] = pack_h2(s[rs][kk*2][2],   s[rs][kk*2][3]);
                pa[rs][2] = pack_h2(s[rs][kk*2+1][0], s[rs][kk*2+1][1]);
                pa[rs][3] = pack_h2(s[rs][kk*2+1][2], s[rs][kk*2+1][3]);
            }
#pragma unroll
            for (int pj = 0; pj < 4; ++pj) {
                int r = kk * 16 + vrow;
                int gc = pj * 2 + vsel;
                uint32_t ad = st + A_VOFF + r * 128 +
                              (((uint32_t)(gc ^ (r & 7))) << 4);
                uint32_t tv[4];
                ldm_x4_t(tv, ad);
#pragma unroll
                for (int rs = 0; rs < 2; ++rs) {
                    mma_f16(oacc[rs][pj*2],   pa[rs], tv[0], tv[1]);
                    mma_f16(oacc[rs][pj*2+1], pa[rs], tv[2], tv[3]);
                }
            }
        }
    }

#pragma unroll
    for (int rs = 0; rs < 2; ++rs) {
#pragma unroll
        for (int ri = 0; ri < 2; ++ri) {
            float inv = 1.0f / li[rs][ri];
            int srow = q0 + w * 32 + rs * 16 + g + ri * 8;
            size_t rowo = ((size_t)(b * S_) + srow) * D_ + h * HD_;
#pragma unroll
            for (int dj = 0; dj < 8; ++dj) {
                int c = dj * 8 + 2 * t;
                uint32_t hp = pack_h2(oacc[rs][dj][ri*2] * inv,
                                      oacc[rs][dj][ri*2+1] * inv);
                *(uint32_t*)(o_ + rowo + c) = hp;
            }
        }
    }
}

// ---------------------------------------------------------------------------
extern "C" void kernel_launch(void* const* d_in, const int* in_sizes, int n_in,
                              void* d_out, int out_size)
{
    (void)in_sizes; (void)n_in; (void)out_size;
    const float* x     = (const float*)d_in[0];
    const float* w_qkv = (const float*)d_in[1];
    const float* w_out = (const float*)d_in[2];
    const float* b_out = (const float*)d_in[3];
    float* out = (float*)d_out;

    float *p_qkv, *p_if;
    __half *p_x, *p_wq, *p_wo, *p_q, *p_k, *p_v, *p_o;
    cudaGetSymbolAddress((void**)&p_qkv, g_qkv);
    cudaGetSymbolAddress((void**)&p_if,  g_invfreq);
    cudaGetSymbolAddress((void**)&p_x,   g_x16);
    cudaGetSymbolAddress((void**)&p_wq,  g_wq16);
    cudaGetSymbolAddress((void**)&p_wo,  g_wo16);
    cudaGetSymbolAddress((void**)&p_q,   g_q16);
    cudaGetSymbolAddress((void**)&p_k,   g_k16);
    cudaGetSymbolAddress((void**)&p_v,   g_v16);
    cudaGetSymbolAddress((void**)&p_o,   g_o16);

    cudaFuncSetAttribute(gemm_f16,
        cudaFuncAttributeMaxDynamicSharedMemorySize, GEMM_SMEM);
    cudaFuncSetAttribute(attn_f16,
        cudaFuncAttributeMaxDynamicSharedMemorySize, ATT_SMEM);

    // 0) rope table + one segmented fp16 conversion launch
    init_invfreq<<<1, 32>>>(p_if);
    cvt_f16_all<<<(CVT_S2 + 255) / 256, 256>>>(x, w_qkv, w_out,
                                               p_x, p_wq, p_wo);
    // 1) QKV projection (fp16 in, fp32 out)
    {
        dim3 grid(NQKV / 128, M_ / 128);
        gemm_f16<<<grid, 256, GEMM_SMEM>>>(p_x, p_wq, nullptr, p_qkv,
                                           M_, NQKV, D_);
    }
    // 2) RoPE -> fp16 q/k/v [B,H,S,64]
    {
        int total = B_ * S_ * H_ * 32;
        rope_f16<<<(total + 255) / 256, 256>>>(p_qkv, p_if, p_q, p_k, p_v);
    }
    // 3) flash attention (fp16 tensor cores)
    {
        dim3 grid(S_ / 128, H_, B_);
        attn_f16<<<grid, 128, ATT_SMEM>>>(p_q, p_k, p_v, p_o);
    }
    // 4) output projection + bias
    {
        dim3 grid(D_ / 128, M_ / 128);
        gemm_f16<<<grid, 256, GEMM_SMEM>>>(p_o, p_wo, b_out, out,
                                           M_, D_, D_);
    }
}

// round 16
// speedup vs baseline: 1.1040x; 1.0016x over previous
#include <cuda_runtime.h>
#include <cuda_fp16.h>
#include <math.h>
#include <cstdint>

#define B_   2
#define S_   2048
#define D_   1024
#define H_   16
#define HD_  64
#define M_   (B_ * S_)      // 4096
#define NQKV (3 * D_)       // 3072

// ---------------- scratch (static device globals; no allocation) ----------
__device__ __half g_qkv16[(size_t)M_ * NQKV];    // fp16 [B*S, 3D]
__device__ __half g_x16[(size_t)M_ * D_];
__device__ __half g_wq16[(size_t)NQKV * D_];
__device__ __half g_wo16[(size_t)D_ * D_];
__device__ __half g_q16[(size_t)M_ * D_];        // [B,H,S,64]
__device__ __half g_k16[(size_t)M_ * D_];        // [B,H,S,64]
__device__ __half g_v16[(size_t)M_ * D_];        // [B,H,S,64]
__device__ __half g_o16[(size_t)M_ * D_];        // [B*S, D]
__device__ float  g_invfreq[32];

// =====================  helpers  ===========================================
__device__ __forceinline__ uint32_t smem_u32(const void* p) {
    uint32_t a;
    asm("{ .reg .u64 t; cvta.to.shared.u64 t, %1; cvt.u32.u64 %0, t; }"
        : "=r"(a) : "l"(p));
    return a;
}
__device__ __forceinline__ void ldm_x4(uint32_t (&r)[4], uint32_t addr) {
    asm volatile("ldmatrix.sync.aligned.m8n8.x4.shared.b16 {%0,%1,%2,%3}, [%4];"
        : "=r"(r[0]), "=r"(r[1]), "=r"(r[2]), "=r"(r[3]) : "r"(addr));
}
__device__ __forceinline__ void ldm_x4_t(uint32_t (&r)[4], uint32_t addr) {
    asm volatile("ldmatrix.sync.aligned.m8n8.x4.trans.shared.b16 {%0,%1,%2,%3}, [%4];"
        : "=r"(r[0]), "=r"(r[1]), "=r"(r[2]), "=r"(r[3]) : "r"(addr));
}
__device__ __forceinline__ void mma_f16(float (&d)[4], const uint32_t (&a)[4],
                                        uint32_t b0, uint32_t b1) {
    asm volatile(
        "mma.sync.aligned.m16n8k16.row.col.f32.f16.f16.f32 "
        "{%0,%1,%2,%3}, {%4,%5,%6,%7}, {%8,%9}, {%0,%1,%2,%3};"
        : "+f"(d[0]), "+f"(d[1]), "+f"(d[2]), "+f"(d[3])
        : "r"(a[0]), "r"(a[1]), "r"(a[2]), "r"(a[3]), "r"(b0), "r"(b1));
}
__device__ __forceinline__ void cp16(uint32_t saddr, const void* gaddr) {
    asm volatile("cp.async.cg.shared.global [%0], [%1], 16;"
        :: "r"(saddr), "l"(gaddr));
}
#define CP_COMMIT() asm volatile("cp.async.commit_group;" ::: "memory")
#define CP_WAIT(n)  asm volatile("cp.async.wait_group %0;" :: "n"(n) : "memory")

__device__ __forceinline__ uint32_t pack_h2(float x0, float x1) {
    __half2 h = __floats2half2_rn(x0, x1);
    return *(uint32_t*)&h;
}

// ---------------------------------------------------------------------------
__global__ void init_invfreq(float* invf) {
    int j = threadIdx.x;                    // 0..31
    float tt = (float)(2 * j) * (1.0f / (float)HD_);
    invf[j] = powf(10000.0f, -tt);
}

// ---------------------------------------------------------------------------
// segmented cvt fp32 -> fp16 (rn), 8 elems/thread, one launch for 3 arrays.
// ---------------------------------------------------------------------------
#define CVT_S0 ((M_ * D_) / 8)
#define CVT_S1 (CVT_S0 + (NQKV * D_) / 8)
#define CVT_S2 (CVT_S1 + (D_ * D_) / 8)

__global__ void cvt_f16_all(const float* __restrict__ x,
                            const float* __restrict__ wq,
                            const float* __restrict__ wo,
                            __half* __restrict__ x16,
                            __half* __restrict__ wq16,
                            __half* __restrict__ wo16)
{
    int i = blockIdx.x * blockDim.x + threadIdx.x;
    if (i >= CVT_S2) return;
    const float* src;
    __half* dst;
    int off;
    if (i < CVT_S0)       { src = x;  dst = x16;  off = i; }
    else if (i < CVT_S1)  { src = wq; dst = wq16; off = i - CVT_S0; }
    else                  { src = wo; dst = wo16; off = i - CVT_S1; }
    float4 a = ((const float4*)src)[off * 2];
    float4 b = ((const float4*)src)[off * 2 + 1];
    uint4 o;
    o.x = pack_h2(a.x, a.y);
    o.y = pack_h2(a.z, a.w);
    o.z = pack_h2(b.x, b.y);
    o.w = pack_h2(b.z, b.w);
    ((uint4*)dst)[off] = o;
}

// ---------------------------------------------------------------------------
// GEMM mainloop (NT) fp16: CTA 128x128, 8 warps, warp tile 64x32. K-chunk 64,
// 3-stage cp.async (32KB/stage), 2 CTAs/SM.
// ---------------------------------------------------------------------------
#define G_BOFF 16384
#define G_STG  32768
#define GEMM_SMEM (3 * G_STG)      // 98304

#define GEMM_F16_MAINLOOP()                                                    \
    extern __shared__ char sm[];                                               \
    const uint32_t sb = smem_u32(sm);                                          \
    const int tid  = threadIdx.x;                                              \
    const int lane = tid & 31;                                                 \
    const int w    = tid >> 5;                                                 \
    const int m0 = blockIdx.y * 128;                                           \
    const int n0 = blockIdx.x * 128;                                           \
    const int wm = (w & 1) * 64;                                               \
    const int wn = (w >> 1) * 32;                                              \
    float acc[4][4][4];                                                        \
    _Pragma("unroll")                                                          \
    for (int mi = 0; mi < 4; ++mi)                                             \
        _Pragma("unroll")                                                      \
        for (int nj = 0; nj < 4; ++nj)                                         \
            _Pragma("unroll")                                                  \
            for (int q = 0; q < 4; ++q) acc[mi][nj][q] = 0.f;                  \
    const int nch = K >> 6;                                                    \
    auto issue = [&](int kc, int stg) {                                        \
        uint32_t st = sb + stg * G_STG;                                        \
        _Pragma("unroll")                                                      \
        for (int it = 0; it < 4; ++it) {                                       \
            int idx = tid + it * 256;                                          \
            int r = idx >> 3, c = idx & 7;                                     \
            uint32_t so = r * 128 + (((uint32_t)(c ^ (r & 7))) << 4);          \
            cp16(st + so, A + (size_t)(m0 + r) * K + kc * 64 + c * 8);         \
        }                                                                      \
        _Pragma("unroll")                                                      \
        for (int it = 0; it < 4; ++it) {                                       \
            int idx = tid + it * 256;                                          \
            int r = idx >> 3, c = idx & 7;                                     \
            uint32_t so = r * 128 + (((uint32_t)(c ^ (r & 7))) << 4);          \
            cp16(st + G_BOFF + so, Bw + (size_t)(n0 + r) * K + kc * 64 + c * 8); \
        }                                                                      \
        CP_COMMIT();                                                           \
    };                                                                         \
    issue(0, 0);                                                               \
    if (nch > 1) issue(1, 1);                                                  \
    const int arow = (lane & 7) + ((lane >> 3) & 1) * 8;                       \
    const int asel = lane >> 4;                                                \
    const int brow = (lane & 7) + ((lane >> 4) & 1) * 8;                       \
    const int bsel = (lane >> 3) & 1;                                          \
    for (int kc = 0; kc < nch; ++kc) {                                         \
        if (kc + 1 < nch) { CP_WAIT(1); }                                      \
        else              { CP_WAIT(0); }                                      \
        __syncthreads();                                                       \
        if (kc + 2 < nch) issue(kc + 2, (kc + 2) % 3);                         \
        const uint32_t st = sb + (kc % 3) * G_STG;                             \
        _Pragma("unroll")                                                      \
        for (int ks = 0; ks < 4; ++ks) {                                       \
            uint32_t bf[4][2];                                                 \
            _Pragma("unroll")                                                  \
            for (int pi = 0; pi < 2; ++pi) {                                   \
                int r = wn + pi * 16 + brow;                                   \
                int gc = ks * 2 + bsel;                                        \
                uint32_t ad = st + G_BOFF + r * 128 +                          \
                              (((uint32_t)(gc ^ (r & 7))) << 4);               \
                uint32_t tr[4];                                                \
                ldm_x4(tr, ad);                                                \
                bf[pi*2][0] = tr[0]; bf[pi*2][1] = tr[1];                      \
                bf[pi*2+1][0] = tr[2]; bf[pi*2+1][1] = tr[3];                  \
            }                                                                  \
            _Pragma("unroll")                                                  \
            for (int mi = 0; mi < 4; ++mi) {                                   \
                int r = wm + mi * 16 + arow;                                   \
                int gc = ks * 2 + asel;                                        \
                uint32_t ad = st + r * 128 + (((uint32_t)(gc ^ (r & 7))) << 4);\
                uint32_t af[4];                                                \
                ldm_x4(af, ad);                                                \
                _Pragma("unroll")                                              \
                for (int nj = 0; nj < 4; ++nj)                                 \
                    mma_f16(acc[mi][nj], af, bf[nj][0], bf[nj][1]);            \
            }                                                                  \
        }                                                                      \
    }

// fp32-output GEMM (out projection, with bias)
__global__ void __launch_bounds__(256, 2) gemm_f16(
    const __half* __restrict__ A, const __half* __restrict__ Bw,
    const float* __restrict__ bias, float* __restrict__ C,
    int M, int N, int K)
{
    GEMM_F16_MAINLOOP()

    const int g = lane >> 2;
    const int c0 = (lane & 3) * 2;
#pragma unroll
    for (int mi = 0; mi < 4; ++mi) {
#pragma unroll
        for (int nj = 0; nj < 4; ++nj) {
            int m = m0 + wm + mi * 16 + g;
            int n = n0 + wn + nj * 8 + c0;
            float b0 = bias ? bias[n] : 0.f;
            float b1 = bias ? bias[n + 1] : 0.f;
            float2 v0 = {acc[mi][nj][0] + b0, acc[mi][nj][1] + b1};
            float2 v1 = {acc[mi][nj][2] + b0, acc[mi][nj][3] + b1};
            *(float2*)(C + (size_t)m * N + n)       = v0;
            *(float2*)(C + (size_t)(m + 8) * N + n) = v1;
        }
    }
}

// fp16-output GEMM (QKV projection, no bias)
__global__ void __launch_bounds__(256, 2) gemm_f16h(
    const __half* __restrict__ A, const __half* __restrict__ Bw,
    __half* __restrict__ C, int M, int N, int K)
{
    GEMM_F16_MAINLOOP()

    const int g = lane >> 2;
    const int c0 = (lane & 3) * 2;
#pragma unroll
    for (int mi = 0; mi < 4; ++mi) {
#pragma unroll
        for (int nj = 0; nj < 4; ++nj) {
            int m = m0 + wm + mi * 16 + g;
            int n = n0 + wn + nj * 8 + c0;
            uint32_t h0 = pack_h2(acc[mi][nj][0], acc[mi][nj][1]);
            uint32_t h1 = pack_h2(acc[mi][nj][2], acc[mi][nj][3]);
            *(uint32_t*)(C + (size_t)m * N + n)       = h0;
            *(uint32_t*)(C + (size_t)(m + 8) * N + n) = h1;
        }
    }
}

// ---------------------------------------------------------------------------
// RoPE: fp16 qkv -> fp16 q/k/v in [B,H,S,64]. Math in fp32 (same formulas).
// ---------------------------------------------------------------------------
__global__ void rope_f16(const __half* __restrict__ qkv,
                         const float* __restrict__ invfreq,
                         __half* __restrict__ q16, __half* __restrict__ k16,
                         __half* __restrict__ v16)
{
    int idx = blockIdx.x * blockDim.x + threadIdx.x;
    if (idx >= B_ * S_ * H_ * 32) return;
    int j = idx & 31;
    int h = (idx >> 5) & (H_ - 1);
    int s = (idx >> 9) & (S_ - 1);
    int b = idx >> 20;

    float ang = (float)s * invfreq[j];
    float cs, sn;
    sincosf(ang, &sn, &cs);

    const __half* row = qkv + ((size_t)(b * S_ + s)) * NQKV + h * HD_;
    float2 qv = __half22float2(*(const __half2*)(row + 2 * j));
    float2 kv = __half22float2(*(const __half2*)(row + D_ + 2 * j));
    __half2 vh = *(const __half2*)(row + 2 * D_ + 2 * j);

    size_t o = (((size_t)(b * H_ + h)) * S_ + s) * HD_;
    const float qs = 0.125f;
    q16[o + j]      = __float2half_rn((qv.x * cs - qv.y * sn) * qs);
    q16[o + 32 + j] = __float2half_rn((qv.x * sn + qv.y * cs) * qs);
    k16[o + j]      = __float2half_rn(kv.x * cs - kv.y * sn);
    k16[o + 32 + j] = __float2half_rn(kv.x * sn + kv.y * cs);
    *(__half2*)(v16 + o + 2 * j) = vh;
}

// ---------------------------------------------------------------------------
// Flash attention fp16. 128 threads (4 warps), 32 q-rows/warp (q-tile 128),
// kv-tile 64, 3-stage cp.async, 2 CTAs/SM. (round 12/15, proven)
// ---------------------------------------------------------------------------
#define A_VOFF 8192
#define A_STG  16384
#define ATT_SMEM (3 * A_STG)       // 49152

__global__ void __launch_bounds__(128, 2) attn_f16(
    const __half* __restrict__ q_, const __half* __restrict__ k_,
    const __half* __restrict__ v_, __half* __restrict__ o_)
{
    extern __shared__ char sm[];
    const uint32_t sb = smem_u32(sm);
    const int tid  = threadIdx.x;
    const int lane = tid & 31;
    const int w    = tid >> 5;
    const int g    = lane >> 2;
    const int t    = lane & 3;
    const int q0 = blockIdx.x * 128;
    const int h  = blockIdx.y;
    const int b  = blockIdx.z;
    const size_t bh = ((size_t)(b * H_ + h)) * S_;

    const int frow = (lane & 7) + ((lane >> 3) & 1) * 8;
    const int fsel = lane >> 4;
    const int brow = (lane & 7) + ((lane >> 4) & 1) * 8;
    const int bsel = (lane >> 3) & 1;
    const int vrow = (lane & 7) + ((lane >> 3) & 1) * 8;
    const int vsel = lane >> 4;

#pragma unroll
    for (int it = 0; it < 8; ++it) {
        int idx = tid + it * 128;
        int r = idx >> 3, c = idx & 7;
        uint32_t so = r * 128 + (((uint32_t)(c ^ (r & 7))) << 4);
        cp16(sb + so, q_ + (bh + q0 + r) * HD_ + c * 8);
    }
    CP_COMMIT();
    CP_WAIT(0);
    __syncthreads();

    uint32_t qf[2][4][4];
#pragma unroll
    for (int rs = 0; rs < 2; ++rs) {
        int r = w * 32 + rs * 16 + frow;
#pragma unroll
        for (int ks = 0; ks < 4; ++ks) {
            int gc = ks * 2 + fsel;
            uint32_t ad = sb + r * 128 + (((uint32_t)(gc ^ (r & 7))) << 4);
            ldm_x4(qf[rs][ks], ad);
        }
    }
    __syncthreads();

    auto issue_kv = [&](int n0k, int stg) {
        uint32_t st = sb + stg * A_STG;
#pragma unroll
        for (int it = 0; it < 4; ++it) {
            int idx = tid + it * 128;
            int r = idx >> 3, c = idx & 7;
            uint32_t so = r * 128 + (((uint32_t)(c ^ (r & 7))) << 4);
            cp16(st + so, k_ + (bh + n0k + r) * HD_ + c * 8);
        }
#pragma unroll
        for (int it = 0; it < 4; ++it) {
            int idx = tid + it * 128;
            int r = idx >> 3, c = idx & 7;
            uint32_t so = r * 128 + (((uint32_t)(c ^ (r & 7))) << 4);
            cp16(st + A_VOFF + so, v_ + (bh + n0k + r) * HD_ + c * 8);
        }
        CP_COMMIT();
    };

    issue_kv(0, 0);
    issue_kv(64, 1);

    float oacc[2][8][4];
    float mx[2][2] = {{-1e30f, -1e30f}, {-1e30f, -1e30f}};
    float li[2][2] = {{0.f, 0.f}, {0.f, 0.f}};
#pragma unroll
    for (int rs = 0; rs < 2; ++rs)
#pragma unroll
        for (int dj = 0; dj < 8; ++dj)
#pragma unroll
            for (int q = 0; q < 4; ++q) oacc[rs][dj][q] = 0.f;

    const int nkv = S_ / 64;
    for (int kc = 0; kc < nkv; ++kc) {
        if (kc + 1 < nkv) { CP_WAIT(1); }
        else              { CP_WAIT(0); }
        __syncthreads();
        if (kc + 2 < nkv) issue_kv((kc + 2) * 64, (kc + 2) % 3);
        const uint32_t st = sb + (kc % 3) * A_STG;

        float s[2][8][4];
#pragma unroll
        for (int rs = 0; rs < 2; ++rs)
#pragma unroll
            for (int nj = 0; nj < 8; ++nj)
#pragma unroll
                for (int q = 0; q < 4; ++q) s[rs][nj][q] = 0.f;

#pragma unroll
        for (int ks = 0; ks < 4; ++ks) {
            uint32_t kf[8][2];
#pragma unroll
            for (int pi = 0; pi < 4; ++pi) {
                int r = pi * 16 + brow;
                int gc = ks * 2 + bsel;
                uint32_t ad = st + r * 128 + (((uint32_t)(gc ^ (r & 7))) << 4);
                uint32_t tr[4];
                ldm_x4(tr, ad);
                kf[pi*2][0] = tr[0]; kf[pi*2][1] = tr[1];
                kf[pi*2+1][0] = tr[2]; kf[pi*2+1][1] = tr[3];
            }
#pragma unroll
            for (int rs = 0; rs < 2; ++rs)
#pragma unroll
                for (int nj = 0; nj < 8; ++nj)
                    mma_f16(s[rs][nj], qf[rs][ks], kf[nj][0], kf[nj][1]);
        }

#pragma unroll
        for (int rs = 0; rs < 2; ++rs) {
#pragma unroll
            for (int ri = 0; ri < 2; ++ri) {
                float rm = -1e30f;
#pragma unroll
                for (int nj = 0; nj < 8; ++nj)
                    rm = fmaxf(rm, fmaxf(s[rs][nj][ri*2], s[rs][nj][ri*2+1]));
                rm = fmaxf(rm, __shfl_xor_sync(0xffffffffu, rm, 1));
                rm = fmaxf(rm, __shfl_xor_sync(0xffffffffu, rm, 2));
                float mn   = fmaxf(mx[rs][ri], rm);
                float corr = __expf(mx[rs][ri] - mn);
                mx[rs][ri] = mn;
                float rsum = 0.f;
#pragma unroll
                for (int nj = 0; nj < 8; ++nj) {
                    float p0 = __expf(s[rs][nj][ri*2]   - mn);
                    float p1 = __expf(s[rs][nj][ri*2+1] - mn);
                    s[rs][nj][ri*2] = p0; s[rs][nj][ri*2+1] = p1;
                    rsum += p0 + p1;
                }
                rsum += __shfl_xor_sync(0xffffffffu, rsum, 1);
                rsum += __shfl_xor_sync(0xffffffffu, rsum, 2);
                li[rs][ri] = li[rs][ri] * corr + rsum;
#pragma unroll
                for (int dj = 0; dj < 8; ++dj) {
                    oacc[rs][dj][ri*2]   *= corr;
                    oacc[rs][dj][ri*2+1] *= corr;
                }
            }
        }

#pragma unroll
        for (int kk = 0; kk < 4; ++kk) {
            uint32_t pa[2][4];
#pragma unroll
            for (int rs = 0; rs < 2; ++rs) {
                pa[rs][0] = pack_h2(s[rs][kk*2][0],   s[rs][kk*2][1]);
                pa[rs][1] = pack_h2(s[rs][kk*2][2],   s[rs][kk*2][3]);
                pa[rs][2] = pack_h2(s[rs][kk*2+1][0], s[rs][kk*2+1][1]);
                pa[rs][3] = pack_h2(s[rs][kk*2+1][2], s[rs][kk*2+1][3]);
            }
#pragma unroll
            for (int pj = 0; pj < 4; ++pj) {
                int r = kk * 16 + vrow;
                int gc = pj * 2 + vsel;
                uint32_t ad = st + A_VOFF + r * 128 +
                              (((uint32_t)(gc ^ (r & 7))) << 4);
                uint32_t tv[4];
                ldm_x4_t(tv, ad);
#pragma unroll
                for (int rs = 0; rs < 2; ++rs) {
                    mma_f16(oacc[rs][pj*2],   pa[rs], tv[0], tv[1]);
                    mma_f16(oacc[rs][pj*2+1], pa[rs], tv[2], tv[3]);
                }
            }
        }
    }

#pragma unroll
    for (int rs = 0; rs < 2; ++rs) {
#pragma unroll
        for (int ri = 0; ri < 2; ++ri) {
            float inv = 1.0f / li[rs][ri];
            int srow = q0 + w * 32 + rs * 16 + g + ri * 8;
            size_t rowo = ((size_t)(b * S_) + srow) * D_ + h * HD_;
#pragma unroll
            for (int dj = 0; dj < 8; ++dj) {
                int c = dj * 8 + 2 * t;
                uint32_t hp = pack_h2(oacc[rs][dj][ri*2] * inv,
                                      oacc[rs][dj][ri*2+1] * inv);
                *(uint32_t*)(o_ + rowo + c) = hp;
            }
        }
    }
}

// ---------------------------------------------------------------------------
extern "C" void kernel_launch(void* const* d_in, const int* in_sizes, int n_in,
                              void* d_out, int out_size)
{
    (void)in_sizes; (void)n_in; (void)out_size;
    const float* x     = (const float*)d_in[0];
    const float* w_qkv = (const float*)d_in[1];
    const float* w_out = (const float*)d_in[2];
    const float* b_out = (const float*)d_in[3];
    float* out = (float*)d_out;

    float* p_if;
    __half *p_qkv, *p_x, *p_wq, *p_wo, *p_q, *p_k, *p_v, *p_o;
    cudaGetSymbolAddress((void**)&p_qkv, g_qkv16);
    cudaGetSymbolAddress((void**)&p_if,  g_invfreq);
    cudaGetSymbolAddress((void**)&p_x,   g_x16);
    cudaGetSymbolAddress((void**)&p_wq,  g_wq16);
    cudaGetSymbolAddress((void**)&p_wo,  g_wo16);
    cudaGetSymbolAddress((void**)&p_q,   g_q16);
    cudaGetSymbolAddress((void**)&p_k,   g_k16);
    cudaGetSymbolAddress((void**)&p_v,   g_v16);
    cudaGetSymbolAddress((void**)&p_o,   g_o16);

    cudaFuncSetAttribute(gemm_f16,
        cudaFuncAttributeMaxDynamicSharedMemorySize, GEMM_SMEM);
    cudaFuncSetAttribute(gemm_f16h,
        cudaFuncAttributeMaxDynamicSharedMemorySize, GEMM_SMEM);
    cudaFuncSetAttribute(attn_f16,
        cudaFuncAttributeMaxDynamicSharedMemorySize, ATT_SMEM);

    // 0) rope table + one segmented fp16 conversion launch
    init_invfreq<<<1, 32>>>(p_if);
    cvt_f16_all<<<(CVT_S2 + 255) / 256, 256>>>(x, w_qkv, w_out,
                                               p_x, p_wq, p_wo);
    // 1) QKV projection (fp16 in, fp16 out)
    {
        dim3 grid(NQKV / 128, M_ / 128);
        gemm_f16h<<<grid, 256, GEMM_SMEM>>>(p_x, p_wq, p_qkv, M_, NQKV, D_);
    }
    // 2) RoPE -> fp16 q/k/v [B,H,S,64]
    {
        int total = B_ * S_ * H_ * 32;
        rope_f16<<<(total + 255) / 256, 256>>>(p_qkv, p_if, p_q, p_k, p_v);
    }
    // 3) flash attention (fp16 tensor cores)
    {
        dim3 grid(S_ / 128, H_, B_);
        attn_f16<<<grid, 128, ATT_SMEM>>>(p_q, p_k, p_v, p_o);
    }
    // 4) output projection + bias (fp32 out)
    {
        dim3 grid(D_ / 128, M_ / 128);
        gemm_f16<<<grid, 256, GEMM_SMEM>>>(p_o, p_wo, b_out, out,
                                           M_, D_, D_);
    }
}

// round 17
// speedup vs baseline: 1.1236x; 1.0178x over previous
#include <cuda_runtime.h>
#include <cuda_fp16.h>
#include <math.h>
#include <cstdint>

#define B_   2
#define S_   2048
#define D_   1024
#define H_   16
#define HD_  64
#define M_   (B_ * S_)      // 4096
#define NQKV (3 * D_)       // 3072

// ---------------- scratch (static device globals; no allocation) ----------
__device__ __half g_qkv16[(size_t)M_ * NQKV];    // fp16 [B*S, 3D]
__device__ __half g_x16[(size_t)M_ * D_];
__device__ __half g_wq16[(size_t)NQKV * D_];
__device__ __half g_wo16[(size_t)D_ * D_];
__device__ __half g_q16[(size_t)M_ * D_];        // [B,H,S,64]
__device__ __half g_k16[(size_t)M_ * D_];        // [B,H,S,64]
__device__ __half g_o16[(size_t)M_ * D_];        // [B*S, D]
__device__ float  g_invfreq[32];

// =====================  helpers  ===========================================
__device__ __forceinline__ uint32_t smem_u32(const void* p) {
    uint32_t a;
    asm("{ .reg .u64 t; cvta.to.shared.u64 t, %1; cvt.u32.u64 %0, t; }"
        : "=r"(a) : "l"(p));
    return a;
}
__device__ __forceinline__ void ldm_x4(uint32_t (&r)[4], uint32_t addr) {
    asm volatile("ldmatrix.sync.aligned.m8n8.x4.shared.b16 {%0,%1,%2,%3}, [%4];"
        : "=r"(r[0]), "=r"(r[1]), "=r"(r[2]), "=r"(r[3]) : "r"(addr));
}
__device__ __forceinline__ void ldm_x4_t(uint32_t (&r)[4], uint32_t addr) {
    asm volatile("ldmatrix.sync.aligned.m8n8.x4.trans.shared.b16 {%0,%1,%2,%3}, [%4];"
        : "=r"(r[0]), "=r"(r[1]), "=r"(r[2]), "=r"(r[3]) : "r"(addr));
}
__device__ __forceinline__ void mma_f16(float (&d)[4], const uint32_t (&a)[4],
                                        uint32_t b0, uint32_t b1) {
    asm volatile(
        "mma.sync.aligned.m16n8k16.row.col.f32.f16.f16.f32 "
        "{%0,%1,%2,%3}, {%4,%5,%6,%7}, {%8,%9}, {%0,%1,%2,%3};"
        : "+f"(d[0]), "+f"(d[1]), "+f"(d[2]), "+f"(d[3])
        : "r"(a[0]), "r"(a[1]), "r"(a[2]), "r"(a[3]), "r"(b0), "r"(b1));
}
__device__ __forceinline__ void cp16(uint32_t saddr, const void* gaddr) {
    asm volatile("cp.async.cg.shared.global [%0], [%1], 16;"
        :: "r"(saddr), "l"(gaddr));
}
#define CP_COMMIT() asm volatile("cp.async.commit_group;" ::: "memory")
#define CP_WAIT(n)  asm volatile("cp.async.wait_group %0;" :: "n"(n) : "memory")

__device__ __forceinline__ uint32_t pack_h2(float x0, float x1) {
    __half2 h = __floats2half2_rn(x0, x1);
    return *(uint32_t*)&h;
}

// ---------------------------------------------------------------------------
__global__ void init_invfreq(float* invf) {
    int j = threadIdx.x;                    // 0..31
    float tt = (float)(2 * j) * (1.0f / (float)HD_);
    invf[j] = powf(10000.0f, -tt);
}

// ---------------------------------------------------------------------------
// segmented cvt fp32 -> fp16 (rn), 8 elems/thread, one launch for 3 arrays.
// ---------------------------------------------------------------------------
#define CVT_S0 ((M_ * D_) / 8)
#define CVT_S1 (CVT_S0 + (NQKV * D_) / 8)
#define CVT_S2 (CVT_S1 + (D_ * D_) / 8)

__global__ void cvt_f16_all(const float* __restrict__ x,
                            const float* __restrict__ wq,
                            const float* __restrict__ wo,
                            __half* __restrict__ x16,
                            __half* __restrict__ wq16,
                            __half* __restrict__ wo16)
{
    int i = blockIdx.x * blockDim.x + threadIdx.x;
    if (i >= CVT_S2) return;
    const float* src;
    __half* dst;
    int off;
    if (i < CVT_S0)       { src = x;  dst = x16;  off = i; }
    else if (i < CVT_S1)  { src = wq; dst = wq16; off = i - CVT_S0; }
    else                  { src = wo; dst = wo16; off = i - CVT_S1; }
    float4 a = ((const float4*)src)[off * 2];
    float4 b = ((const float4*)src)[off * 2 + 1];
    uint4 o;
    o.x = pack_h2(a.x, a.y);
    o.y = pack_h2(a.z, a.w);
    o.z = pack_h2(b.x, b.y);
    o.w = pack_h2(b.z, b.w);
    ((uint4*)dst)[off] = o;
}

// ---------------------------------------------------------------------------
// GEMM mainloop (NT) fp16: CTA 128x128, 8 warps, warp tile 64x32. K-chunk 64,
// 3-stage cp.async (32KB/stage), 2 CTAs/SM.
// ---------------------------------------------------------------------------
#define G_BOFF 16384
#define G_STG  32768
#define GEMM_SMEM (3 * G_STG)      // 98304

#define GEMM_F16_MAINLOOP()                                                    \
    extern __shared__ char sm[];                                               \
    const uint32_t sb = smem_u32(sm);                                          \
    const int tid  = threadIdx.x;                                              \
    const int lane = tid & 31;                                                 \
    const int w    = tid >> 5;                                                 \
    const int m0 = blockIdx.y * 128;                                           \
    const int n0 = blockIdx.x * 128;                                           \
    const int wm = (w & 1) * 64;                                               \
    const int wn = (w >> 1) * 32;                                              \
    float acc[4][4][4];                                                        \
    _Pragma("unroll")                                                          \
    for (int mi = 0; mi < 4; ++mi)                                             \
        _Pragma("unroll")                                                      \
        for (int nj = 0; nj < 4; ++nj)                                         \
            _Pragma("unroll")                                                  \
            for (int q = 0; q < 4; ++q) acc[mi][nj][q] = 0.f;                  \
    const int nch = K >> 6;                                                    \
    auto issue = [&](int kc, int stg) {                                        \
        uint32_t st = sb + stg * G_STG;                                        \
        _Pragma("unroll")                                                      \
        for (int it = 0; it < 4; ++it) {                                       \
            int idx = tid + it * 256;                                          \
            int r = idx >> 3, c = idx & 7;                                     \
            uint32_t so = r * 128 + (((uint32_t)(c ^ (r & 7))) << 4);          \
            cp16(st + so, A + (size_t)(m0 + r) * K + kc * 64 + c * 8);         \
        }                                                                      \
        _Pragma("unroll")                                                      \
        for (int it = 0; it < 4; ++it) {                                       \
            int idx = tid + it * 256;                                          \
            int r = idx >> 3, c = idx & 7;                                     \
            uint32_t so = r * 128 + (((uint32_t)(c ^ (r & 7))) << 4);          \
            cp16(st + G_BOFF + so, Bw + (size_t)(n0 + r) * K + kc * 64 + c * 8); \
        }                                                                      \
        CP_COMMIT();                                                           \
    };                                                                         \
    issue(0, 0);                                                               \
    if (nch > 1) issue(1, 1);                                                  \
    const int arow = (lane & 7) + ((lane >> 3) & 1) * 8;                       \
    const int asel = lane >> 4;                                                \
    const int brow = (lane & 7) + ((lane >> 4) & 1) * 8;                       \
    const int bsel = (lane >> 3) & 1;                                          \
    for (int kc = 0; kc < nch; ++kc) {                                         \
        if (kc + 1 < nch) { CP_WAIT(1); }                                      \
        else              { CP_WAIT(0); }                                      \
        __syncthreads();                                                       \
        if (kc + 2 < nch) issue(kc + 2, (kc + 2) % 3);                         \
        const uint32_t st = sb + (kc % 3) * G_STG;                             \
        _Pragma("unroll")                                                      \
        for (int ks = 0; ks < 4; ++ks) {                                       \
            uint32_t bf[4][2];                                                 \
            _Pragma("unroll")                                                  \
            for (int pi = 0; pi < 2; ++pi) {                                   \
                int r = wn + pi * 16 + brow;                                   \
                int gc = ks * 2 + bsel;                                        \
                uint32_t ad = st + G_BOFF + r * 128 +                          \
                              (((uint32_t)(gc ^ (r & 7))) << 4);               \
                uint32_t tr[4];                                                \
                ldm_x4(tr, ad);                                                \
                bf[pi*2][0] = tr[0]; bf[pi*2][1] = tr[1];                      \
                bf[pi*2+1][0] = tr[2]; bf[pi*2+1][1] = tr[3];                  \
            }                                                                  \
            _Pragma("unroll")                                                  \
            for (int mi = 0; mi < 4; ++mi) {                                   \
                int r = wm + mi * 16 + arow;                                   \
                int gc = ks * 2 + asel;                                        \
                uint32_t ad = st + r * 128 + (((uint32_t)(gc ^ (r & 7))) << 4);\
                uint32_t af[4];                                                \
                ldm_x4(af, ad);                                                \
                _Pragma("unroll")                                              \
                for (int nj = 0; nj < 4; ++nj)                                 \
                    mma_f16(acc[mi][nj], af, bf[nj][0], bf[nj][1]);            \
            }                                                                  \
        }                                                                      \
    }

// fp32-output GEMM (out projection, with bias)
__global__ void __launch_bounds__(256, 2) gemm_f16(
    const __half* __restrict__ A, const __half* __restrict__ Bw,
    const float* __restrict__ bias, float* __restrict__ C,
    int M, int N, int K)
{
    GEMM_F16_MAINLOOP()

    const int g = lane >> 2;
    const int c0 = (lane & 3) * 2;
#pragma unroll
    for (int mi = 0; mi < 4; ++mi) {
#pragma unroll
        for (int nj = 0; nj < 4; ++nj) {
            int m = m0 + wm + mi * 16 + g;
            int n = n0 + wn + nj * 8 + c0;
            float b0 = bias ? bias[n] : 0.f;
            float b1 = bias ? bias[n + 1] : 0.f;
            float2 v0 = {acc[mi][nj][0] + b0, acc[mi][nj][1] + b1};
            float2 v1 = {acc[mi][nj][2] + b0, acc[mi][nj][3] + b1};
            *(float2*)(C + (size_t)m * N + n)       = v0;
            *(float2*)(C + (size_t)(m + 8) * N + n) = v1;
        }
    }
}

// fp16-output GEMM (QKV projection, no bias)
__global__ void __launch_bounds__(256, 2) gemm_f16h(
    const __half* __restrict__ A, const __half* __restrict__ Bw,
    __half* __restrict__ C, int M, int N, int K)
{
    GEMM_F16_MAINLOOP()

    const int g = lane >> 2;
    const int c0 = (lane & 3) * 2;
#pragma unroll
    for (int mi = 0; mi < 4; ++mi) {
#pragma unroll
        for (int nj = 0; nj < 4; ++nj) {
            int m = m0 + wm + mi * 16 + g;
            int n = n0 + wn + nj * 8 + c0;
            uint32_t h0 = pack_h2(acc[mi][nj][0], acc[mi][nj][1]);
            uint32_t h1 = pack_h2(acc[mi][nj][2], acc[mi][nj][3]);
            *(uint32_t*)(C + (size_t)m * N + n)       = h0;
            *(uint32_t*)(C + (size_t)(m + 8) * N + n) = h1;
        }
    }
}

// ---------------------------------------------------------------------------
// RoPE (q/k only): fp16 qkv -> fp16 q/k in [B,H,S,64]. j-pair vectorized:
// each thread handles j = 2j', 2j'+1; all stores are __half2.
// Same formulas / rounding as round 16 (q/k bit-identical).
// ---------------------------------------------------------------------------
__global__ void rope_qk(const __half* __restrict__ qkv,
                        const float* __restrict__ invfreq,
                        __half* __restrict__ q16, __half* __restrict__ k16)
{
    int idx = blockIdx.x * blockDim.x + threadIdx.x;
    if (idx >= B_ * S_ * H_ * 16) return;
    int jp = idx & 15;                 // j' = 0..15 -> j = 2j', 2j'+1
    int h = (idx >> 4) & (H_ - 1);
    int s = (idx >> 8) & (S_ - 1);
    int b = idx >> 19;
    int j0 = 2 * jp;

    float ang0 = (float)s * invfreq[j0];
    float ang1 = (float)s * invfreq[j0 + 1];
    float cs0, sn0, cs1, sn1;
    sincosf(ang0, &sn0, &cs0);
    sincosf(ang1, &sn1, &cs1);

    const __half* row = qkv + ((size_t)(b * S_ + s)) * NQKV + h * HD_;
    // q pairs: (x[4jp], x[4jp+1]) and (x[4jp+2], x[4jp+3])
    float2 qa = __half22float2(*(const __half2*)(row + 4 * jp));
    float2 qb = __half22float2(*(const __half2*)(row + 4 * jp + 2));
    float2 ka = __half22float2(*(const __half2*)(row + D_ + 4 * jp));
    float2 kb = __half22float2(*(const __half2*)(row + D_ + 4 * jp + 2));

    size_t o = (((size_t)(b * H_ + h)) * S_ + s) * HD_;
    const float qs = 0.125f;
    // outputs j0, j0+1 (lo half) and 32+j0, 32+j0+1 (hi half)
    *(uint32_t*)(q16 + o + j0) =
        pack_h2((qa.x * cs0 - qa.y * sn0) * qs, (qb.x * cs1 - qb.y * sn1) * qs);
    *(uint32_t*)(q16 + o + 32 + j0) =
        pack_h2((qa.x * sn0 + qa.y * cs0) * qs, (qb.x * sn1 + qb.y * cs1) * qs);
    *(uint32_t*)(k16 + o + j0) =
        pack_h2(ka.x * cs0 - ka.y * sn0, kb.x * cs1 - kb.y * sn1);
    *(uint32_t*)(k16 + o + 32 + j0) =
        pack_h2(ka.x * sn0 + ka.y * cs0, kb.x * sn1 + kb.y * cs1);
}

// ---------------------------------------------------------------------------
// Flash attention fp16. 128 threads (4 warps), 32 q-rows/warp (q-tile 128),
// kv-tile 64, 3-stage cp.async, 2 CTAs/SM. V read directly from qkv16
// (row stride NQKV, column offset 2D + h*64).
// ---------------------------------------------------------------------------
#define A_VOFF 8192
#define A_STG  16384
#define ATT_SMEM (3 * A_STG)       // 49152

__global__ void __launch_bounds__(128, 2) attn_f16(
    const __half* __restrict__ q_, const __half* __restrict__ k_,
    const __half* __restrict__ qkv_, __half* __restrict__ o_)
{
    extern __shared__ char sm[];
    const uint32_t sb = smem_u32(sm);
    const int tid  = threadIdx.x;
    const int lane = tid & 31;
    const int w    = tid >> 5;
    const int g    = lane >> 2;
    const int t    = lane & 3;
    const int q0 = blockIdx.x * 128;
    const int h  = blockIdx.y;
    const int b  = blockIdx.z;
    const size_t bh = ((size_t)(b * H_ + h)) * S_;
    const __half* vsrc = qkv_ + (size_t)(b * S_) * NQKV + 2 * D_ + h * HD_;

    const int frow = (lane & 7) + ((lane >> 3) & 1) * 8;
    const int fsel = lane >> 4;
    const int brow = (lane & 7) + ((lane >> 4) & 1) * 8;
    const int bsel = (lane >> 3) & 1;
    const int vrow = (lane & 7) + ((lane >> 3) & 1) * 8;
    const int vsel = lane >> 4;

#pragma unroll
    for (int it = 0; it < 8; ++it) {
        int idx = tid + it * 128;
        int r = idx >> 3, c = idx & 7;
        uint32_t so = r * 128 + (((uint32_t)(c ^ (r & 7))) << 4);
        cp16(sb + so, q_ + (bh + q0 + r) * HD_ + c * 8);
    }
    CP_COMMIT();
    CP_WAIT(0);
    __syncthreads();

    uint32_t qf[2][4][4];
#pragma unroll
    for (int rs = 0; rs < 2; ++rs) {
        int r = w * 32 + rs * 16 + frow;
#pragma unroll
        for (int ks = 0; ks < 4; ++ks) {
            int gc = ks * 2 + fsel;
            uint32_t ad = sb + r * 128 + (((uint32_t)(gc ^ (r & 7))) << 4);
            ldm_x4(qf[rs][ks], ad);
        }
    }
    __syncthreads();

    auto issue_kv = [&](int n0k, int stg) {
        uint32_t st = sb + stg * A_STG;
#pragma unroll
        for (int it = 0; it < 4; ++it) {
            int idx = tid + it * 128;
            int r = idx >> 3, c = idx & 7;
            uint32_t so = r * 128 + (((uint32_t)(c ^ (r & 7))) << 4);
            cp16(st + so, k_ + (bh + n0k + r) * HD_ + c * 8);
        }
#pragma unroll
        for (int it = 0; it < 4; ++it) {
            int idx = tid + it * 128;
            int r = idx >> 3, c = idx & 7;
            uint32_t so = r * 128 + (((uint32_t)(c ^ (r & 7))) << 4);
            cp16(st + A_VOFF + so,
                 vsrc + (size_t)(n0k + r) * NQKV + c * 8);
        }
        CP_COMMIT();
    };

    issue_kv(0, 0);
    issue_kv(64, 1);

    float oacc[2][8][4];
    float mx[2][2] = {{-1e30f, -1e30f}, {-1e30f, -1e30f}};
    float li[2][2] = {{0.f, 0.f}, {0.f, 0.f}};
#pragma unroll
    for (int rs = 0; rs < 2; ++rs)
#pragma unroll
        for (int dj = 0; dj < 8; ++dj)
#pragma unroll
            for (int q = 0; q < 4; ++q) oacc[rs][dj][q] = 0.f;

    const int nkv = S_ / 64;
    for (int kc = 0; kc < nkv; ++kc) {
        if (kc + 1 < nkv) { CP_WAIT(1); }
        else              { CP_WAIT(0); }
        __syncthreads();
        if (kc + 2 < nkv) issue_kv((kc + 2) * 64, (kc + 2) % 3);
        const uint32_t st = sb + (kc % 3) * A_STG;

        float s[2][8][4];
#pragma unroll
        for (int rs = 0; rs < 2; ++rs)
#pragma unroll
            for (int nj = 0; nj < 8; ++nj)
#pragma unroll
                for (int q = 0; q < 4; ++q) s[rs][nj][q] = 0.f;

#pragma unroll
        for (int ks = 0; ks < 4; ++ks) {
            uint32_t kf[8][2];
#pragma unroll
            for (int pi = 0; pi < 4; ++pi) {
                int r = pi * 16 + brow;
                int gc = ks * 2 + bsel;
                uint32_t ad = st + r * 128 + (((uint32_t)(gc ^ (r & 7))) << 4);
                uint32_t tr[4];
                ldm_x4(tr, ad);
                kf[pi*2][0] = tr[0]; kf[pi*2][1] = tr[1];
                kf[pi*2+1][0] = tr[2]; kf[pi*2+1][1] = tr[3];
            }
#pragma unroll
            for (int rs = 0; rs < 2; ++rs)
#pragma unroll
                for (int nj = 0; nj < 8; ++nj)
                    mma_f16(s[rs][nj], qf[rs][ks], kf[nj][0], kf[nj][1]);
        }

#pragma unroll
        for (int rs = 0; rs < 2; ++rs) {
#pragma unroll
            for (int ri = 0; ri < 2; ++ri) {
                float rm = -1e30f;
#pragma unroll
                for (int nj = 0; nj < 8; ++nj)
                    rm = fmaxf(rm, fmaxf(s[rs][nj][ri*2], s[rs][nj][ri*2+1]));
                rm = fmaxf(rm, __shfl_xor_sync(0xffffffffu, rm, 1));
                rm = fmaxf(rm, __shfl_xor_sync(0xffffffffu, rm, 2));
                float mn   = fmaxf(mx[rs][ri], rm);
                float corr = __expf(mx[rs][ri] - mn);
                mx[rs][ri] = mn;
                float rsum = 0.f;
#pragma unroll
                for (int nj = 0; nj < 8; ++nj) {
                    float p0 = __expf(s[rs][nj][ri*2]   - mn);
                    float p1 = __expf(s[rs][nj][ri*2+1] - mn);
                    s[rs][nj][ri*2] = p0; s[rs][nj][ri*2+1] = p1;
                    rsum += p0 + p1;
                }
                rsum += __shfl_xor_sync(0xffffffffu, rsum, 1);
                rsum += __shfl_xor_sync(0xffffffffu, rsum, 2);
                li[rs][ri] = li[rs][ri] * corr + rsum;
#pragma unroll
                for (int dj = 0; dj < 8; ++dj) {
                    oacc[rs][dj][ri*2]   *= corr;
                    oacc[rs][dj][ri*2+1] *= corr;
                }
            }
        }

#pragma unroll
        for (int kk = 0; kk < 4; ++kk) {
            uint32_t pa[2][4];
#pragma unroll
            for (int rs = 0; rs < 2; ++rs) {
                pa[rs][0] = pack_h2(s[rs][kk*2][0],   s[rs][kk*2][1]);
                pa[rs][1] = pack_h2(s[rs][kk*2][2],   s[rs][kk*2][3]);
                pa[rs][2] = pack_h2(s[rs][kk*2+1][0], s[rs][kk*2+1][1]);
                pa[rs][3] = pack_h2(s[rs][kk*2+1][2], s[rs][kk*2+1][3]);
            }
#pragma unroll
            for (int pj = 0; pj < 4; ++pj) {
                int r = kk * 16 + vrow;
                int gc = pj * 2 + vsel;
                uint32_t ad = st + A_VOFF + r * 128 +
                              (((uint32_t)(gc ^ (r & 7))) << 4);
                uint32_t tv[4];
                ldm_x4_t(tv, ad);
#pragma unroll
                for (int rs = 0; rs < 2; ++rs) {
                    mma_f16(oacc[rs][pj*2],   pa[rs], tv[0], tv[1]);
                    mma_f16(oacc[rs][pj*2+1], pa[rs], tv[2], tv[3]);
                }
            }
        }
    }

#pragma unroll
    for (int rs = 0; rs < 2; ++rs) {
#pragma unroll
        for (int ri = 0; ri < 2; ++ri) {
            float inv = 1.0f / li[rs][ri];
            int srow = q0 + w * 32 + rs * 16 + g + ri * 8;
            size_t rowo = ((size_t)(b * S_) + srow) * D_ + h * HD_;
#pragma unroll
            for (int dj = 0; dj < 8; ++dj) {
                int c = dj * 8 + 2 * t;
                uint32_t hp = pack_h2(oacc[rs][dj][ri*2] * inv,
                                      oacc[rs][dj][ri*2+1] * inv);
                *(uint32_t*)(o_ + rowo + c) = hp;
            }
        }
    }
}

// ---------------------------------------------------------------------------
extern "C" void kernel_launch(void* const* d_in, const int* in_sizes, int n_in,
                              void* d_out, int out_size)
{
    (void)in_sizes; (void)n_in; (void)out_size;
    const float* x     = (const float*)d_in[0];
    const float* w_qkv = (const float*)d_in[1];
    const float* w_out = (const float*)d_in[2];
    const float* b_out = (const float*)d_in[3];
    float* out = (float*)d_out;

    float* p_if;
    __half *p_qkv, *p_x, *p_wq, *p_wo, *p_q, *p_k, *p_o;
    cudaGetSymbolAddress((void**)&p_qkv, g_qkv16);
    cudaGetSymbolAddress((void**)&p_if,  g_invfreq);
    cudaGetSymbolAddress((void**)&p_x,   g_x16);
    cudaGetSymbolAddress((void**)&p_wq,  g_wq16);
    cudaGetSymbolAddress((void**)&p_wo,  g_wo16);
    cudaGetSymbolAddress((void**)&p_q,   g_q16);
    cudaGetSymbolAddress((void**)&p_k,   g_k16);
    cudaGetSymbolAddress((void**)&p_o,   g_o16);

    cudaFuncSetAttribute(gemm_f16,
        cudaFuncAttributeMaxDynamicSharedMemorySize, GEMM_SMEM);
    cudaFuncSetAttribute(gemm_f16h,
        cudaFuncAttributeMaxDynamicSharedMemorySize, GEMM_SMEM);
    cudaFuncSetAttribute(attn_f16,
        cudaFuncAttributeMaxDynamicSharedMemorySize, ATT_SMEM);

    // 0) rope table + one segmented fp16 conversion launch
    init_invfreq<<<1, 32>>>(p_if);
    cvt_f16_all<<<(CVT_S2 + 255) / 256, 256>>>(x, w_qkv, w_out,
                                               p_x, p_wq, p_wo);
    // 1) QKV projection (fp16 in, fp16 out)
    {
        dim3 grid(NQKV / 128, M_ / 128);
        gemm_f16h<<<grid, 256, GEMM_SMEM>>>(p_x, p_wq, p_qkv, M_, NQKV, D_);
    }
    // 2) RoPE (q/k only) -> fp16 [B,H,S,64]
    {
        int total = B_ * S_ * H_ * 16;
        rope_qk<<<(total + 255) / 256, 256>>>(p_qkv, p_if, p_q, p_k);
    }
    // 3) flash attention (V streamed straight from qkv16)
    {
        dim3 grid(S_ / 128, H_, B_);
        attn_f16<<<grid, 128, ATT_SMEM>>>(p_q, p_k, p_qkv, p_o);
    }
    // 4) output projection + bias (fp32 out)
    {
        dim3 grid(D_ / 128, M_ / 128);
        gemm_f16<<<grid, 256, GEMM_SMEM>>>(p_o, p_wo, b_out, out,
                                           M_, D_, D_);
    }
}